// round 5
// baseline (speedup 1.0000x reference)
#include <cuda_runtime.h>
#include <cuda_bf16.h>
#include <cstdint>

#define NNODES 100000
#define EPS_BN 1e-5f

// Scratch (allocation-free rule: __device__ globals)
__device__ __align__(16) float g_xs [(size_t)NNODES * 128];  // xw * dinv[row]
__device__ __align__(16) float g_agg[(size_t)NNODES * 128];  // accumulator
__device__ __align__(16) float g_h  [(size_t)NNODES * 128];  // activations
__device__ float g_deg   [NNODES];
__device__ float g_dinv  [NNODES];
__device__ float g_invdeg[NNODES];

// ---------------------------------------------------------------------------
// Vectorized global reduction (sm_90+): 4 floats in one L2 atomic op
// ---------------------------------------------------------------------------
__device__ __forceinline__ void red_add_v4(float4* addr, float a, float b, float c, float d) {
    asm volatile("red.global.add.v4.f32 [%0], {%1, %2, %3, %4};"
                 :: "l"(addr), "f"(a), "f"(b), "f"(c), "f"(d) : "memory");
}

// ---------------------------------------------------------------------------
// Degree pipeline
// ---------------------------------------------------------------------------
__global__ void deg_init_kernel(float* __restrict__ deg, int N) {
    int i = blockIdx.x * blockDim.x + threadIdx.x;
    if (i < N) deg[i] = 1.0f;  // self-loop
}

__global__ void deg_count_kernel(const int* __restrict__ dst, float* __restrict__ deg, int E) {
    int i = blockIdx.x * blockDim.x + threadIdx.x;
    if (i < E) atomicAdd(&deg[dst[i]], 1.0f);
}

__global__ void deg_final_kernel(const float* __restrict__ deg,
                                 float* __restrict__ dinv, float* __restrict__ invdeg, int N) {
    int i = blockIdx.x * blockDim.x + threadIdx.x;
    if (i < N) {
        float d = deg[i];
        dinv[i]   = rsqrtf(d);
        invdeg[i] = 1.0f / d;
    }
}

// ---------------------------------------------------------------------------
// GEMM + fused epilogue:
//   acc = H @ W          (H: [N,K] row-major, W: [K,FO] row-major)
//   xs  = acc * dinv[row]
//   agg = acc * invdeg[row] + bias[col]   (self-loop term + bias init)
// Block: 32 rows, 256 threads as 16(col)x16(row), each thread 2 rows x FO/16 cols.
// ---------------------------------------------------------------------------
template <int K, int FO>
__global__ __launch_bounds__(256)
void gemm_kernel(const float* __restrict__ H, const float* __restrict__ W,
                 const float* __restrict__ bias,
                 const float* __restrict__ dinv, const float* __restrict__ invdeg,
                 float* __restrict__ xs, float* __restrict__ agg, int N)
{
    constexpr int BM = 32;
    constexpr int TN = FO / 16;
    __shared__ __align__(16) float As[BM * K];
    __shared__ __align__(16) float Ws[K * FO];

    const int tid = threadIdx.x;
    const int rowbase = blockIdx.x * BM;

    // Load W tile (whole weight matrix), float4-coalesced
    for (int i = tid; i < (K * FO) / 4; i += 256)
        reinterpret_cast<float4*>(Ws)[i] = reinterpret_cast<const float4*>(W)[i];

    // Load A tile (32 rows), float4-coalesced, zero-fill OOB rows
    for (int i = tid; i < (BM * K) / 4; i += 256) {
        int r  = i / (K / 4);
        int kc = i % (K / 4);
        int row = rowbase + r;
        float4 v = make_float4(0.f, 0.f, 0.f, 0.f);
        if (row < N) v = reinterpret_cast<const float4*>(H)[row * (K / 4) + kc];
        reinterpret_cast<float4*>(As)[i] = v;
    }
    __syncthreads();

    const int tcol = tid & 15;
    const int trow = tid >> 4;

    float acc[2][TN];
#pragma unroll
    for (int r = 0; r < 2; r++)
#pragma unroll
        for (int j = 0; j < TN; j++) acc[r][j] = 0.f;

    const float* a0p = &As[(trow * 2 + 0) * K];
    const float* a1p = &As[(trow * 2 + 1) * K];
    const int cbase = tcol * TN;

#pragma unroll 8
    for (int k = 0; k < K; k++) {
        float a0 = a0p[k];
        float a1 = a1p[k];
#pragma unroll
        for (int j = 0; j < TN; j++) {
            float wv = Ws[k * FO + cbase + j];
            acc[0][j] = fmaf(a0, wv, acc[0][j]);
            acc[1][j] = fmaf(a1, wv, acc[1][j]);
        }
    }

#pragma unroll
    for (int r = 0; r < 2; r++) {
        int row = rowbase + trow * 2 + r;
        if (row >= N) continue;
        float dv = dinv[row];
        float iv = invdeg[row];
#pragma unroll
        for (int j = 0; j < TN; j++) {
            int col = cbase + j;
            float v = acc[r][j];
            xs [row * FO + col] = v * dv;
            agg[row * FO + col] = v * iv + bias[col];
        }
    }
}

// ---------------------------------------------------------------------------
// Edge scatter: agg[dst] += xs[src] * dinv[dst]   (dinv[src] already folded)
// One thread per (edge, float4-chunk). fo4 = FO/4 is a power of two.
// ---------------------------------------------------------------------------
__global__ __launch_bounds__(256)
void scatter_kernel(const float4* __restrict__ xs,
                    const int* __restrict__ src, const int* __restrict__ dst,
                    const float* __restrict__ dinv,
                    float4* __restrict__ agg, int E, int logfo4)
{
    int i = blockIdx.x * 256 + threadIdx.x;
    int items = E << logfo4;
    if (i >= items) return;
    int fo4 = 1 << logfo4;
    int e = i >> logfo4;
    int c = i & (fo4 - 1);
    int s = src[e];
    int d = dst[e];
    float4 v = xs[s * fo4 + c];
    float w = dinv[d];
    red_add_v4(&agg[d * fo4 + c], v.x * w, v.y * w, v.z * w, v.w * w);
}

// ---------------------------------------------------------------------------
// Fused BatchNorm (inference) + ReLU, float4 vectorized
// ---------------------------------------------------------------------------
__global__ __launch_bounds__(256)
void bnrelu_kernel(const float4* __restrict__ agg,
                   const float4* __restrict__ g, const float4* __restrict__ be,
                   const float4* __restrict__ m, const float4* __restrict__ v,
                   float4* __restrict__ h, int N, int logfo4)
{
    int i = blockIdx.x * 256 + threadIdx.x;
    int items = N << logfo4;
    if (i >= items) return;
    int fo4 = 1 << logfo4;
    int j = i & (fo4 - 1);
    float4 a  = agg[i];
    float4 gm = g[j];
    float4 bb = be[j];
    float4 mm = m[j];
    float4 vv = v[j];
    float4 o;
    o.x = fmaxf(fmaf((a.x - mm.x) * rsqrtf(vv.x + EPS_BN), gm.x, bb.x), 0.f);
    o.y = fmaxf(fmaf((a.y - mm.y) * rsqrtf(vv.y + EPS_BN), gm.y, bb.y), 0.f);
    o.z = fmaxf(fmaf((a.z - mm.z) * rsqrtf(vv.z + EPS_BN), gm.z, bb.z), 0.f);
    o.w = fmaxf(fmaf((a.w - mm.w) * rsqrtf(vv.w + EPS_BN), gm.w, bb.w), 0.f);
    h[i] = o;
}

// ---------------------------------------------------------------------------
// Host launcher
// ---------------------------------------------------------------------------
static inline int cdiv(int a, int b) { return (a + b - 1) / b; }

extern "C" void kernel_launch(void* const* d_in, const int* in_sizes, int n_in,
                              void* d_out, int out_size)
{
    const float* x  = (const float*)d_in[0];
    const int*   ei = (const int*)d_in[1];
    const int N = in_sizes[0] / 128;
    const int E = in_sizes[1] / 2;
    const int* src = ei;
    const int* dst = ei + E;

    const float *w[5], *b[5], *gg[4], *bb[4], *mm[4], *vv[4];
    int idx = 2;
    for (int l = 0; l < 5; l++) { w[l] = (const float*)d_in[idx++]; b[l] = (const float*)d_in[idx++]; }
    for (int l = 0; l < 4; l++) {
        gg[l] = (const float*)d_in[idx++]; bb[l] = (const float*)d_in[idx++];
        mm[l] = (const float*)d_in[idx++]; vv[l] = (const float*)d_in[idx++];
    }

    float *xs, *agg, *h, *deg, *dinv, *invdeg;
    cudaGetSymbolAddress((void**)&xs,     g_xs);
    cudaGetSymbolAddress((void**)&agg,    g_agg);
    cudaGetSymbolAddress((void**)&h,      g_h);
    cudaGetSymbolAddress((void**)&deg,    g_deg);
    cudaGetSymbolAddress((void**)&dinv,   g_dinv);
    cudaGetSymbolAddress((void**)&invdeg, g_invdeg);

    // Degrees
    deg_init_kernel<<<cdiv(N, 256), 256>>>(deg, N);
    deg_count_kernel<<<cdiv(E, 256), 256>>>(dst, deg, E);
    deg_final_kernel<<<cdiv(N, 256), 256>>>(deg, dinv, invdeg, N);

    const int gemm_blocks = cdiv(N, 32);

    // ---- Layer 1: 128 -> 64, BN+ReLU ----
    gemm_kernel<128, 64><<<gemm_blocks, 256>>>(x, w[0], b[0], dinv, invdeg, xs, agg, N);
    scatter_kernel<<<cdiv(E << 4, 256), 256>>>((const float4*)xs, src, dst, dinv, (float4*)agg, E, 4);
    bnrelu_kernel<<<cdiv(N << 4, 256), 256>>>((const float4*)agg, (const float4*)gg[0], (const float4*)bb[0],
                                              (const float4*)mm[0], (const float4*)vv[0], (float4*)h, N, 4);

    // ---- Layer 2: 64 -> 128, BN+ReLU ----
    gemm_kernel<64, 128><<<gemm_blocks, 256>>>(h, w[1], b[1], dinv, invdeg, xs, agg, N);
    scatter_kernel<<<cdiv(E << 5, 256), 256>>>((const float4*)xs, src, dst, dinv, (float4*)agg, E, 5);
    bnrelu_kernel<<<cdiv(N << 5, 256), 256>>>((const float4*)agg, (const float4*)gg[1], (const float4*)bb[1],
                                              (const float4*)mm[1], (const float4*)vv[1], (float4*)h, N, 5);

    // ---- Layer 3: 128 -> 64, BN+ReLU ----
    gemm_kernel<128, 64><<<gemm_blocks, 256>>>(h, w[2], b[2], dinv, invdeg, xs, agg, N);
    scatter_kernel<<<cdiv(E << 4, 256), 256>>>((const float4*)xs, src, dst, dinv, (float4*)agg, E, 4);
    bnrelu_kernel<<<cdiv(N << 4, 256), 256>>>((const float4*)agg, (const float4*)gg[2], (const float4*)bb[2],
                                              (const float4*)mm[2], (const float4*)vv[2], (float4*)h, N, 4);

    // ---- Layer 4: 64 -> 32, BN+ReLU ----
    gemm_kernel<64, 32><<<gemm_blocks, 256>>>(h, w[3], b[3], dinv, invdeg, xs, agg, N);
    scatter_kernel<<<cdiv(E << 3, 256), 256>>>((const float4*)xs, src, dst, dinv, (float4*)agg, E, 3);
    bnrelu_kernel<<<cdiv(N << 3, 256), 256>>>((const float4*)agg, (const float4*)gg[3], (const float4*)bb[3],
                                              (const float4*)mm[3], (const float4*)vv[3], (float4*)h, N, 3);

    // ---- Layer 5: 32 -> 16, no BN/ReLU, agg == d_out ----
    float* out = (float*)d_out;
    gemm_kernel<32, 16><<<gemm_blocks, 256>>>(h, w[4], b[4], dinv, invdeg, xs, out, N);
    scatter_kernel<<<cdiv(E << 2, 256), 256>>>((const float4*)xs, src, dst, dinv, (float4*)out, E, 2);
}

// round 9
// speedup vs baseline: 1.5543x; 1.5543x over previous
#include <cuda_runtime.h>
#include <cuda_bf16.h>
#include <cstdint>

#define NNODES 100000
#define NEDGES 1600000
#define EPS_BN 1e-5f

// ---------------------------------------------------------------------------
// Scratch (__device__ globals; allocation-free rule)
// ---------------------------------------------------------------------------
__device__ __align__(16) float g_xs  [(size_t)NNODES * 128];  // xw * dinv[row]
__device__ __align__(16) float g_self[(size_t)NNODES * 128];  // xw/deg + bias
__device__ __align__(16) float g_h   [(size_t)NNODES * 128];  // activations
__device__ float g_dinv  [NNODES];
__device__ float g_invdeg[NNODES];
__device__ int   g_cnt   [NNODES];
__device__ int   g_row   [NNODES + 1];
__device__ int   g_fill  [NNODES];
__device__ int   g_csrsrc[NEDGES];
__device__ int   g_bsums [128];

// ---------------------------------------------------------------------------
// CSR build pipeline
// ---------------------------------------------------------------------------
__global__ void zero_cnt_kernel(int* __restrict__ cnt, int N) {
    int i = blockIdx.x * blockDim.x + threadIdx.x;
    if (i < N) cnt[i] = 0;
}

__global__ void count_kernel(const int* __restrict__ dst, int* __restrict__ cnt, int E) {
    int i = blockIdx.x * blockDim.x + threadIdx.x;
    if (i < E) atomicAdd(&cnt[dst[i]], 1);
}

// Block-level exclusive scan: 1024 elements/block (256 thr x 4), Kogge-Stone.
__global__ void scan1_kernel(const int* __restrict__ cnt, int* __restrict__ rowp,
                             int* __restrict__ bsums, int N) {
    __shared__ int s[256];
    int tid = threadIdx.x;
    int base = blockIdx.x * 1024 + tid * 4;
    int v0 = (base + 0 < N) ? cnt[base + 0] : 0;
    int v1 = (base + 1 < N) ? cnt[base + 1] : 0;
    int v2 = (base + 2 < N) ? cnt[base + 2] : 0;
    int v3 = (base + 3 < N) ? cnt[base + 3] : 0;
    int t = v0 + v1 + v2 + v3;
    int val = t;
    for (int off = 1; off < 256; off <<= 1) {
        s[tid] = val; __syncthreads();
        if (tid >= off) val += s[tid - off];
        __syncthreads();
    }
    int excl = val - t;
    if (base + 0 < N) rowp[base + 0] = excl;
    if (base + 1 < N) rowp[base + 1] = excl + v0;
    if (base + 2 < N) rowp[base + 2] = excl + v0 + v1;
    if (base + 3 < N) rowp[base + 3] = excl + v0 + v1 + v2;
    if (tid == 255) bsums[blockIdx.x] = val;  // block total
}

__global__ void scan2_kernel(int* __restrict__ bsums, int nb) {
    __shared__ int s[128];
    int tid = threadIdx.x;
    int t = (tid < nb) ? bsums[tid] : 0;
    int val = t;
    for (int off = 1; off < 128; off <<= 1) {
        s[tid] = val; __syncthreads();
        if (tid >= off) val += s[tid - off];
        __syncthreads();
    }
    if (tid < nb) bsums[tid] = val - t;  // exclusive
}

// Finalize rowptr, seed fill counters, compute dinv/invdeg.
__global__ void scan3_kernel(int* __restrict__ rowp, int* __restrict__ fill,
                             const int* __restrict__ bsums, const int* __restrict__ cnt,
                             float* __restrict__ dinv, float* __restrict__ invdeg,
                             int N, int E) {
    int i = blockIdx.x * blockDim.x + threadIdx.x;
    if (i < N) {
        int r = rowp[i] + bsums[i >> 10];
        rowp[i] = r;
        fill[i] = r;
        float d = (float)(cnt[i] + 1);  // +1 self-loop
        dinv[i]   = rsqrtf(d);
        invdeg[i] = 1.0f / d;
    }
    if (i == 0) rowp[N] = E;
}

__global__ void fill_kernel(const int* __restrict__ src, const int* __restrict__ dst,
                            int* __restrict__ fill, int* __restrict__ csrsrc, int E) {
    int e = blockIdx.x * blockDim.x + threadIdx.x;
    if (e < E) {
        int d = dst[e];
        int pos = atomicAdd(&fill[d], 1);
        csrsrc[pos] = src[e];
    }
}

// ---------------------------------------------------------------------------
// GEMM + fused epilogue:  acc = H @ W
//   xs   = acc * dinv[row]
//   self = acc * invdeg[row] + bias[col]
// BM=64 rows/block, 256 threads = 16(col) x 16(row-group), 4 rows x TNC cols each.
// ---------------------------------------------------------------------------
template <int K, int FO>
__global__ __launch_bounds__(256)
void gemm_kernel(const float* __restrict__ H, const float* __restrict__ W,
                 const float* __restrict__ bias,
                 const float* __restrict__ dinv, const float* __restrict__ invdeg,
                 float* __restrict__ xs, float* __restrict__ self, int N)
{
    constexpr int BM  = 64;
    constexpr int TNC = FO / 16;  // 8,4,2,1
    extern __shared__ float smem[];
    float* As = smem;             // [BM][K]
    float* Ws = smem + BM * K;    // [K][FO]

    const int tid = threadIdx.x;
    const int rowbase = blockIdx.x * BM;

    for (int i = tid; i < (K * FO) / 4; i += 256)
        reinterpret_cast<float4*>(Ws)[i] = reinterpret_cast<const float4*>(W)[i];

    for (int i = tid; i < (BM * K) / 4; i += 256) {
        int r  = i / (K / 4);
        int kc = i % (K / 4);
        int row = rowbase + r;
        float4 v = make_float4(0.f, 0.f, 0.f, 0.f);
        if (row < N) v = reinterpret_cast<const float4*>(H)[row * (K / 4) + kc];
        reinterpret_cast<float4*>(As)[i] = v;
    }
    __syncthreads();

    const int tcol = tid & 15;
    const int trow = tid >> 4;
    const int cbase = tcol * TNC;

    float acc[4][TNC];
#pragma unroll
    for (int r = 0; r < 4; r++)
#pragma unroll
        for (int j = 0; j < TNC; j++) acc[r][j] = 0.f;

    const float* a0 = &As[(trow * 4 + 0) * K];
    const float* a1 = &As[(trow * 4 + 1) * K];
    const float* a2 = &As[(trow * 4 + 2) * K];
    const float* a3 = &As[(trow * 4 + 3) * K];

#pragma unroll 8
    for (int k = 0; k < K; k++) {
        float av0 = a0[k], av1 = a1[k], av2 = a2[k], av3 = a3[k];
        if (TNC >= 4) {
#pragma unroll
            for (int jg = 0; jg < TNC / 4; jg++) {
                float4 wv = *reinterpret_cast<const float4*>(&Ws[k * FO + cbase + jg * 4]);
                int j = jg * 4;
                acc[0][j+0] = fmaf(av0, wv.x, acc[0][j+0]); acc[0][j+1] = fmaf(av0, wv.y, acc[0][j+1]);
                acc[0][j+2] = fmaf(av0, wv.z, acc[0][j+2]); acc[0][j+3] = fmaf(av0, wv.w, acc[0][j+3]);
                acc[1][j+0] = fmaf(av1, wv.x, acc[1][j+0]); acc[1][j+1] = fmaf(av1, wv.y, acc[1][j+1]);
                acc[1][j+2] = fmaf(av1, wv.z, acc[1][j+2]); acc[1][j+3] = fmaf(av1, wv.w, acc[1][j+3]);
                acc[2][j+0] = fmaf(av2, wv.x, acc[2][j+0]); acc[2][j+1] = fmaf(av2, wv.y, acc[2][j+1]);
                acc[2][j+2] = fmaf(av2, wv.z, acc[2][j+2]); acc[2][j+3] = fmaf(av2, wv.w, acc[2][j+3]);
                acc[3][j+0] = fmaf(av3, wv.x, acc[3][j+0]); acc[3][j+1] = fmaf(av3, wv.y, acc[3][j+1]);
                acc[3][j+2] = fmaf(av3, wv.z, acc[3][j+2]); acc[3][j+3] = fmaf(av3, wv.w, acc[3][j+3]);
            }
        } else {
#pragma unroll
            for (int j = 0; j < TNC; j++) {
                float wv = Ws[k * FO + cbase + j];
                acc[0][j] = fmaf(av0, wv, acc[0][j]);
                acc[1][j] = fmaf(av1, wv, acc[1][j]);
                acc[2][j] = fmaf(av2, wv, acc[2][j]);
                acc[3][j] = fmaf(av3, wv, acc[3][j]);
            }
        }
    }

#pragma unroll
    for (int r = 0; r < 4; r++) {
        int row = rowbase + trow * 4 + r;
        if (row >= N) continue;
        float dv = dinv[row];
        float iv = invdeg[row];
#pragma unroll
        for (int j = 0; j < TNC; j++) {
            int col = cbase + j;
            float v = acc[r][j];
            xs  [(size_t)row * FO + col] = v * dv;
            self[(size_t)row * FO + col] = fmaf(v, iv, bias[col]);
        }
    }
}

// ---------------------------------------------------------------------------
// CSR gather: warp per node. Lanes split (edge x float4-chunk).
//   out = maybe_bnrelu( edgesum * dinv[n] + self[n] )
// ---------------------------------------------------------------------------
template <int FO, bool BN>
__global__ __launch_bounds__(256)
void gather_kernel(const float4* __restrict__ xs, const float4* __restrict__ selfterm,
                   const int* __restrict__ csrsrc, const int* __restrict__ rowp,
                   const float* __restrict__ dinv,
                   const float4* __restrict__ g, const float4* __restrict__ be,
                   const float4* __restrict__ m, const float4* __restrict__ vpar,
                   float4* __restrict__ out, int N)
{
    constexpr int FO4 = FO / 4;        // float4 chunks per row (4,8,16,32)
    constexpr int EPW = 32 / FO4;      // edges handled in parallel per warp
    int warp = (blockIdx.x * 256 + threadIdx.x) >> 5;
    int lane = threadIdx.x & 31;
    if (warp >= N) return;
    const int n = warp;
    const int c    = lane & (FO4 - 1);
    const int esub = lane >> (31 - __clz(FO4));  // lane / FO4 (FO4 power of 2)

    int beg = rowp[n], end = rowp[n + 1];
    float4 acc = make_float4(0.f, 0.f, 0.f, 0.f);
    for (int i = beg + esub; i < end; i += EPW) {
        int s = csrsrc[i];
        float4 t = xs[(size_t)s * FO4 + c];
        acc.x += t.x; acc.y += t.y; acc.z += t.z; acc.w += t.w;
    }
#pragma unroll
    for (int off = FO4; off < 32; off <<= 1) {
        acc.x += __shfl_xor_sync(0xffffffffu, acc.x, off);
        acc.y += __shfl_xor_sync(0xffffffffu, acc.y, off);
        acc.z += __shfl_xor_sync(0xffffffffu, acc.z, off);
        acc.w += __shfl_xor_sync(0xffffffffu, acc.w, off);
    }
    if (esub == 0) {
        float dv = dinv[n];
        float4 sf = selfterm[(size_t)n * FO4 + c];
        float4 o;
        o.x = fmaf(acc.x, dv, sf.x);
        o.y = fmaf(acc.y, dv, sf.y);
        o.z = fmaf(acc.z, dv, sf.z);
        o.w = fmaf(acc.w, dv, sf.w);
        if (BN) {
            float4 gm = g[c], bb = be[c], mm = m[c], vv = vpar[c];
            o.x = fmaxf(fmaf((o.x - mm.x) * rsqrtf(vv.x + EPS_BN), gm.x, bb.x), 0.f);
            o.y = fmaxf(fmaf((o.y - mm.y) * rsqrtf(vv.y + EPS_BN), gm.y, bb.y), 0.f);
            o.z = fmaxf(fmaf((o.z - mm.z) * rsqrtf(vv.z + EPS_BN), gm.z, bb.z), 0.f);
            o.w = fmaxf(fmaf((o.w - mm.w) * rsqrtf(vv.w + EPS_BN), gm.w, bb.w), 0.f);
        }
        out[(size_t)n * FO4 + c] = o;
    }
}

// ---------------------------------------------------------------------------
// Host launcher
// ---------------------------------------------------------------------------
static inline int cdiv(int a, int b) { return (a + b - 1) / b; }

template <int K, int FO>
static void launch_gemm(const float* H, const float* W, const float* bias,
                        const float* dinv, const float* invdeg,
                        float* xs, float* self, int N) {
    int smem = (64 * K + K * FO) * 4;
    cudaFuncSetAttribute(gemm_kernel<K, FO>, cudaFuncAttributeMaxDynamicSharedMemorySize, smem);
    gemm_kernel<K, FO><<<cdiv(N, 64), 256, smem>>>(H, W, bias, dinv, invdeg, xs, self, N);
}

extern "C" void kernel_launch(void* const* d_in, const int* in_sizes, int n_in,
                              void* d_out, int out_size)
{
    const float* x  = (const float*)d_in[0];
    const int*   ei = (const int*)d_in[1];
    const int N = in_sizes[0] / 128;
    const int E = in_sizes[1] / 2;
    const int* src = ei;
    const int* dst = ei + E;

    const float *w[5], *b[5], *gg[4], *bb[4], *mm[4], *vv[4];
    int idx = 2;
    for (int l = 0; l < 5; l++) { w[l] = (const float*)d_in[idx++]; b[l] = (const float*)d_in[idx++]; }
    for (int l = 0; l < 4; l++) {
        gg[l] = (const float*)d_in[idx++]; bb[l] = (const float*)d_in[idx++];
        mm[l] = (const float*)d_in[idx++]; vv[l] = (const float*)d_in[idx++];
    }

    float *xs, *self, *h, *dinv, *invdeg;
    int *cnt, *rowp, *fill, *csrsrc, *bsums;
    cudaGetSymbolAddress((void**)&xs,     g_xs);
    cudaGetSymbolAddress((void**)&self,   g_self);
    cudaGetSymbolAddress((void**)&h,      g_h);
    cudaGetSymbolAddress((void**)&dinv,   g_dinv);
    cudaGetSymbolAddress((void**)&invdeg, g_invdeg);
    cudaGetSymbolAddress((void**)&cnt,    g_cnt);
    cudaGetSymbolAddress((void**)&rowp,   g_row);
    cudaGetSymbolAddress((void**)&fill,   g_fill);
    cudaGetSymbolAddress((void**)&csrsrc, g_csrsrc);
    cudaGetSymbolAddress((void**)&bsums,  g_bsums);

    // ---- CSR build + degree terms ----
    zero_cnt_kernel<<<cdiv(N, 256), 256>>>(cnt, N);
    count_kernel<<<cdiv(E, 256), 256>>>(dst, cnt, E);
    const int nb = cdiv(N, 1024);
    scan1_kernel<<<nb, 256>>>(cnt, rowp, bsums, N);
    scan2_kernel<<<1, 128>>>(bsums, nb);
    scan3_kernel<<<cdiv(N, 256), 256>>>(rowp, fill, bsums, cnt, dinv, invdeg, N, E);
    fill_kernel<<<cdiv(E, 256), 256>>>(src, dst, fill, csrsrc, E);

    const int gather_blocks = cdiv(N, 8);  // 8 warps/block, warp per node

    // ---- Layer 1: 128 -> 64, BN+ReLU ----
    launch_gemm<128, 64>(x, w[0], b[0], dinv, invdeg, xs, self, N);
    gather_kernel<64, true><<<gather_blocks, 256>>>((const float4*)xs, (const float4*)self,
        csrsrc, rowp, dinv, (const float4*)gg[0], (const float4*)bb[0],
        (const float4*)mm[0], (const float4*)vv[0], (float4*)h, N);

    // ---- Layer 2: 64 -> 128, BN+ReLU ----
    launch_gemm<64, 128>(h, w[1], b[1], dinv, invdeg, xs, self, N);
    gather_kernel<128, true><<<gather_blocks, 256>>>((const float4*)xs, (const float4*)self,
        csrsrc, rowp, dinv, (const float4*)gg[1], (const float4*)bb[1],
        (const float4*)mm[1], (const float4*)vv[1], (float4*)h, N);

    // ---- Layer 3: 128 -> 64, BN+ReLU ----
    launch_gemm<128, 64>(h, w[2], b[2], dinv, invdeg, xs, self, N);
    gather_kernel<64, true><<<gather_blocks, 256>>>((const float4*)xs, (const float4*)self,
        csrsrc, rowp, dinv, (const float4*)gg[2], (const float4*)bb[2],
        (const float4*)mm[2], (const float4*)vv[2], (float4*)h, N);

    // ---- Layer 4: 64 -> 32, BN+ReLU ----
    launch_gemm<64, 32>(h, w[3], b[3], dinv, invdeg, xs, self, N);
    gather_kernel<32, true><<<gather_blocks, 256>>>((const float4*)xs, (const float4*)self,
        csrsrc, rowp, dinv, (const float4*)gg[3], (const float4*)bb[3],
        (const float4*)mm[3], (const float4*)vv[3], (float4*)h, N);

    // ---- Layer 5: 32 -> 16, no BN, write d_out ----
    float* out = (float*)d_out;
    launch_gemm<32, 16>(h, w[4], b[4], dinv, invdeg, xs, self, N);
    gather_kernel<16, false><<<gather_blocks, 256>>>((const float4*)xs, (const float4*)self,
        csrsrc, rowp, dinv, nullptr, nullptr, nullptr, nullptr, (float4*)out, N);
}

// round 11
// speedup vs baseline: 1.8479x; 1.1889x over previous
#include <cuda_runtime.h>
#include <cuda_bf16.h>
#include <cstdint>

#define NNODES 100000
#define NEDGES 1600000
#define EPS_BN 1e-5f

// ---------------------------------------------------------------------------
// Scratch (__device__ globals; allocation-free rule)
// ---------------------------------------------------------------------------
__device__ __align__(16) float g_xs [(size_t)NNODES * 128];  // xw (layer1: raw, else *dinv)
__device__ __align__(16) float g_h  [(size_t)NNODES * 128];  // activations
__device__ float g_dinv  [NNODES];
__device__ int   g_cnt   [NNODES];
__device__ int   g_row   [NNODES + 1];
__device__ int   g_fill  [NNODES];
__device__ int   g_csrsrc[NEDGES];
__device__ float g_csrw  [NEDGES];
__device__ int   g_bsums [128];

// ---------------------------------------------------------------------------
// CSR build pipeline
// ---------------------------------------------------------------------------
__global__ void count_kernel(const int* __restrict__ dst, int* __restrict__ cnt, int E) {
    int i = blockIdx.x * blockDim.x + threadIdx.x;
    if (i < E) atomicAdd(&cnt[dst[i]], 1);
}

// Block-level exclusive scan: 1024 elements/block (256 thr x 4), Kogge-Stone.
__global__ void scan1_kernel(const int* __restrict__ cnt, int* __restrict__ rowp,
                             int* __restrict__ bsums, int N) {
    __shared__ int s[256];
    int tid = threadIdx.x;
    int base = blockIdx.x * 1024 + tid * 4;
    int v0 = (base + 0 < N) ? cnt[base + 0] : 0;
    int v1 = (base + 1 < N) ? cnt[base + 1] : 0;
    int v2 = (base + 2 < N) ? cnt[base + 2] : 0;
    int v3 = (base + 3 < N) ? cnt[base + 3] : 0;
    int t = v0 + v1 + v2 + v3;
    int val = t;
    for (int off = 1; off < 256; off <<= 1) {
        s[tid] = val; __syncthreads();
        if (tid >= off) val += s[tid - off];
        __syncthreads();
    }
    int excl = val - t;
    if (base + 0 < N) rowp[base + 0] = excl;
    if (base + 1 < N) rowp[base + 1] = excl + v0;
    if (base + 2 < N) rowp[base + 2] = excl + v0 + v1;
    if (base + 3 < N) rowp[base + 3] = excl + v0 + v1 + v2;
    if (tid == 255) bsums[blockIdx.x] = val;
}

__global__ void scan2_kernel(int* __restrict__ bsums, int nb) {
    __shared__ int s[128];
    int tid = threadIdx.x;
    int t = (tid < nb) ? bsums[tid] : 0;
    int val = t;
    for (int off = 1; off < 128; off <<= 1) {
        s[tid] = val; __syncthreads();
        if (tid >= off) val += s[tid - off];
        __syncthreads();
    }
    if (tid < nb) bsums[tid] = val - t;
}

// Finalize rowptr, seed fill counters, compute dinv.
__global__ void scan3_kernel(int* __restrict__ rowp, int* __restrict__ fill,
                             const int* __restrict__ bsums, const int* __restrict__ cnt,
                             float* __restrict__ dinv, int N, int E) {
    int i = blockIdx.x * blockDim.x + threadIdx.x;
    if (i < N) {
        int r = rowp[i] + bsums[i >> 10];
        rowp[i] = r;
        fill[i] = r;
        dinv[i] = rsqrtf((float)(cnt[i] + 1));  // +1 self-loop
    }
    if (i == 0) rowp[N] = E;
}

__global__ void fill_kernel(const int* __restrict__ src, const int* __restrict__ dst,
                            int* __restrict__ fill, const float* __restrict__ dinv,
                            int* __restrict__ csrsrc, float* __restrict__ csrw, int E) {
    int e = blockIdx.x * blockDim.x + threadIdx.x;
    if (e < E) {
        int d = dst[e];
        int s = src[e];
        int pos = atomicAdd(&fill[d], 1);
        csrsrc[pos] = s;
        csrw[pos] = dinv[s];
    }
}

// ---------------------------------------------------------------------------
// GEMM + epilogue:  xs = (H @ W) * (SCALED ? dinv[row] : 1)
// BM=64 rows/block, 256 threads, each thread 4 rows x TNC cols.
// ---------------------------------------------------------------------------
template <int K, int FO, bool SCALED>
__global__ __launch_bounds__(256)
void gemm_kernel(const float* __restrict__ H, const float* __restrict__ W,
                 const float* __restrict__ dinv,
                 float* __restrict__ xs, int N)
{
    constexpr int BM  = 64;
    constexpr int TNC = FO / 16;  // 8,4,2,1
    extern __shared__ float smem[];
    float* As = smem;             // [BM][K]
    float* Ws = smem + BM * K;    // [K][FO]

    const int tid = threadIdx.x;
    const int rowbase = blockIdx.x * BM;

    for (int i = tid; i < (K * FO) / 4; i += 256)
        reinterpret_cast<float4*>(Ws)[i] = reinterpret_cast<const float4*>(W)[i];

    for (int i = tid; i < (BM * K) / 4; i += 256) {
        int r  = i / (K / 4);
        int kc = i % (K / 4);
        int row = rowbase + r;
        float4 v = make_float4(0.f, 0.f, 0.f, 0.f);
        if (row < N) v = reinterpret_cast<const float4*>(H)[row * (K / 4) + kc];
        reinterpret_cast<float4*>(As)[i] = v;
    }
    __syncthreads();

    const int tcol = tid & 15;
    const int trow = tid >> 4;
    const int cbase = tcol * TNC;

    float acc[4][TNC];
#pragma unroll
    for (int r = 0; r < 4; r++)
#pragma unroll
        for (int j = 0; j < TNC; j++) acc[r][j] = 0.f;

    const float* a0 = &As[(trow * 4 + 0) * K];
    const float* a1 = &As[(trow * 4 + 1) * K];
    const float* a2 = &As[(trow * 4 + 2) * K];
    const float* a3 = &As[(trow * 4 + 3) * K];

#pragma unroll 8
    for (int k = 0; k < K; k++) {
        float av0 = a0[k], av1 = a1[k], av2 = a2[k], av3 = a3[k];
        if (TNC >= 4) {
#pragma unroll
            for (int jg = 0; jg < TNC / 4; jg++) {
                float4 wv = *reinterpret_cast<const float4*>(&Ws[k * FO + cbase + jg * 4]);
                int j = jg * 4;
                acc[0][j+0] = fmaf(av0, wv.x, acc[0][j+0]); acc[0][j+1] = fmaf(av0, wv.y, acc[0][j+1]);
                acc[0][j+2] = fmaf(av0, wv.z, acc[0][j+2]); acc[0][j+3] = fmaf(av0, wv.w, acc[0][j+3]);
                acc[1][j+0] = fmaf(av1, wv.x, acc[1][j+0]); acc[1][j+1] = fmaf(av1, wv.y, acc[1][j+1]);
                acc[1][j+2] = fmaf(av1, wv.z, acc[1][j+2]); acc[1][j+3] = fmaf(av1, wv.w, acc[1][j+3]);
                acc[2][j+0] = fmaf(av2, wv.x, acc[2][j+0]); acc[2][j+1] = fmaf(av2, wv.y, acc[2][j+1]);
                acc[2][j+2] = fmaf(av2, wv.z, acc[2][j+2]); acc[2][j+3] = fmaf(av2, wv.w, acc[2][j+3]);
                acc[3][j+0] = fmaf(av3, wv.x, acc[3][j+0]); acc[3][j+1] = fmaf(av3, wv.y, acc[3][j+1]);
                acc[3][j+2] = fmaf(av3, wv.z, acc[3][j+2]); acc[3][j+3] = fmaf(av3, wv.w, acc[3][j+3]);
            }
        } else {
#pragma unroll
            for (int j = 0; j < TNC; j++) {
                float wv = Ws[k * FO + cbase + j];
                acc[0][j] = fmaf(av0, wv, acc[0][j]);
                acc[1][j] = fmaf(av1, wv, acc[1][j]);
                acc[2][j] = fmaf(av2, wv, acc[2][j]);
                acc[3][j] = fmaf(av3, wv, acc[3][j]);
            }
        }
    }

#pragma unroll
    for (int r = 0; r < 4; r++) {
        int row = rowbase + trow * 4 + r;
        if (row >= N) continue;
        float dv = SCALED ? dinv[row] : 1.0f;
#pragma unroll
        for (int j = 0; j < TNC; j++) {
            float v = acc[r][j];
            xs[(size_t)row * FO + cbase + j] = SCALED ? (v * dv) : v;
        }
    }
}

// ---------------------------------------------------------------------------
// CSR gather: warp per node. Lanes split (edge x float4-chunk).
// UNWEIGHTED (xs pre-scaled by dinv[src]):
//   o = dinv[n]*(sum_e xs[src] + xs[n]) + bias, then optional BN+ReLU
// WEIGHTED (xs raw; csrw[i]=dinv[src]):
//   o = dinv[n]*(sum_e csrw*xs[src] + dinv[n]*xs[n]) + bias, ...
// ---------------------------------------------------------------------------
template <int FO, bool BN, bool WEIGHTED>
__global__ __launch_bounds__(256)
void gather_kernel(const float4* __restrict__ xs,
                   const int* __restrict__ csrsrc, const float* __restrict__ csrw,
                   const int* __restrict__ rowp, const float* __restrict__ dinv,
                   const float4* __restrict__ bias,
                   const float4* __restrict__ g, const float4* __restrict__ be,
                   const float4* __restrict__ m, const float4* __restrict__ vpar,
                   float4* __restrict__ out, int N)
{
    constexpr int FO4 = FO / 4;        // 4,8,16,32
    constexpr int EPW = 32 / FO4;
    constexpr int LOG = (FO4 == 4) ? 2 : (FO4 == 8) ? 3 : (FO4 == 16) ? 4 : 5;
    int warp = (blockIdx.x * 256 + threadIdx.x) >> 5;
    int lane = threadIdx.x & 31;
    if (warp >= N) return;
    const int n = warp;
    const int c    = lane & (FO4 - 1);
    const int esub = lane >> LOG;

    int beg = rowp[n], end = rowp[n + 1];
    float4 acc = make_float4(0.f, 0.f, 0.f, 0.f);
    for (int i = beg + esub; i < end; i += EPW) {
        int s = csrsrc[i];
        float4 t = xs[(size_t)s * FO4 + c];
        if (WEIGHTED) {
            float w = csrw[i];
            acc.x = fmaf(w, t.x, acc.x); acc.y = fmaf(w, t.y, acc.y);
            acc.z = fmaf(w, t.z, acc.z); acc.w = fmaf(w, t.w, acc.w);
        } else {
            acc.x += t.x; acc.y += t.y; acc.z += t.z; acc.w += t.w;
        }
    }
    if (esub == 0) {  // self-loop term, added exactly once per chunk
        float4 t = xs[(size_t)n * FO4 + c];
        float w = WEIGHTED ? dinv[n] : 1.0f;
        acc.x = fmaf(w, t.x, acc.x); acc.y = fmaf(w, t.y, acc.y);
        acc.z = fmaf(w, t.z, acc.z); acc.w = fmaf(w, t.w, acc.w);
    }
#pragma unroll
    for (int off = FO4; off < 32; off <<= 1) {
        acc.x += __shfl_xor_sync(0xffffffffu, acc.x, off);
        acc.y += __shfl_xor_sync(0xffffffffu, acc.y, off);
        acc.z += __shfl_xor_sync(0xffffffffu, acc.z, off);
        acc.w += __shfl_xor_sync(0xffffffffu, acc.w, off);
    }
    if (esub == 0) {
        float dv = dinv[n];
        float4 bs = bias[c];
        float4 o;
        o.x = fmaf(acc.x, dv, bs.x);
        o.y = fmaf(acc.y, dv, bs.y);
        o.z = fmaf(acc.z, dv, bs.z);
        o.w = fmaf(acc.w, dv, bs.w);
        if (BN) {
            float4 gm = g[c], bb = be[c], mm = m[c], vv = vpar[c];
            o.x = fmaxf(fmaf((o.x - mm.x) * rsqrtf(vv.x + EPS_BN), gm.x, bb.x), 0.f);
            o.y = fmaxf(fmaf((o.y - mm.y) * rsqrtf(vv.y + EPS_BN), gm.y, bb.y), 0.f);
            o.z = fmaxf(fmaf((o.z - mm.z) * rsqrtf(vv.z + EPS_BN), gm.z, bb.z), 0.f);
            o.w = fmaxf(fmaf((o.w - mm.w) * rsqrtf(vv.w + EPS_BN), gm.w, bb.w), 0.f);
        }
        out[(size_t)n * FO4 + c] = o;
    }
}

// ---------------------------------------------------------------------------
// Host launcher
// ---------------------------------------------------------------------------
static inline int cdiv(int a, int b) { return (a + b - 1) / b; }

template <int K, int FO, bool SCALED>
static void launch_gemm(const float* H, const float* W, const float* dinv,
                        float* xs, int N, cudaStream_t st) {
    int smem = (64 * K + K * FO) * 4;
    cudaFuncSetAttribute(gemm_kernel<K, FO, SCALED>,
                         cudaFuncAttributeMaxDynamicSharedMemorySize, smem);
    gemm_kernel<K, FO, SCALED><<<cdiv(N, 64), 256, smem, st>>>(H, W, dinv, xs, N);
}

extern "C" void kernel_launch(void* const* d_in, const int* in_sizes, int n_in,
                              void* d_out, int out_size)
{
    const float* x  = (const float*)d_in[0];
    const int*   ei = (const int*)d_in[1];
    const int N = in_sizes[0] / 128;
    const int E = in_sizes[1] / 2;
    const int* src = ei;
    const int* dst = ei + E;

    const float *w[5], *b[5], *gg[4], *bb[4], *mm[4], *vv[4];
    int idx = 2;
    for (int l = 0; l < 5; l++) { w[l] = (const float*)d_in[idx++]; b[l] = (const float*)d_in[idx++]; }
    for (int l = 0; l < 4; l++) {
        gg[l] = (const float*)d_in[idx++]; bb[l] = (const float*)d_in[idx++];
        mm[l] = (const float*)d_in[idx++]; vv[l] = (const float*)d_in[idx++];
    }

    float *xs, *h, *dinv, *csrw;
    int *cnt, *rowp, *fill, *csrsrc, *bsums;
    cudaGetSymbolAddress((void**)&xs,     g_xs);
    cudaGetSymbolAddress((void**)&h,      g_h);
    cudaGetSymbolAddress((void**)&dinv,   g_dinv);
    cudaGetSymbolAddress((void**)&cnt,    g_cnt);
    cudaGetSymbolAddress((void**)&rowp,   g_row);
    cudaGetSymbolAddress((void**)&fill,   g_fill);
    cudaGetSymbolAddress((void**)&csrsrc, g_csrsrc);
    cudaGetSymbolAddress((void**)&csrw,   g_csrw);
    cudaGetSymbolAddress((void**)&bsums,  g_bsums);

    // Side stream + events (lazy init happens on the first, non-captured,
    // correctness call; per-call work is identical and deterministic).
    static cudaStream_t s2 = nullptr;
    static cudaEvent_t evFork = nullptr, evJoin = nullptr;
    if (s2 == nullptr) {
        cudaStreamCreateWithFlags(&s2, cudaStreamNonBlocking);
        cudaEventCreateWithFlags(&evFork, cudaEventDisableTiming);
        cudaEventCreateWithFlags(&evJoin, cudaEventDisableTiming);
    }

    // ---- Fork: CSR build + dinv on s2, concurrent with layer-1 GEMM ----
    cudaEventRecord(evFork, 0);
    cudaStreamWaitEvent(s2, evFork, 0);

    cudaMemsetAsync(cnt, 0, (size_t)N * sizeof(int), s2);
    count_kernel<<<cdiv(E, 256), 256, 0, s2>>>(dst, cnt, E);
    const int nb = cdiv(N, 1024);
    scan1_kernel<<<nb, 256, 0, s2>>>(cnt, rowp, bsums, N);
    scan2_kernel<<<1, 128, 0, s2>>>(bsums, nb);
    scan3_kernel<<<cdiv(N, 256), 256, 0, s2>>>(rowp, fill, bsums, cnt, dinv, N, E);
    fill_kernel<<<cdiv(E, 256), 256, 0, s2>>>(src, dst, fill, dinv, csrsrc, csrw, E);

    // Main stream: layer-1 GEMM writes RAW x@w1 (no dinv dependency).
    launch_gemm<128, 64, false>(x, w[0], nullptr, xs, N, 0);

    // ---- Join ----
    cudaEventRecord(evJoin, s2);
    cudaStreamWaitEvent(0, evJoin, 0);

    const int gather_blocks = cdiv(N, 8);  // 8 warps/block, warp per node

    // ---- Layer 1: 128 -> 64 (weighted gather), BN+ReLU ----
    gather_kernel<64, true, true><<<gather_blocks, 256>>>((const float4*)xs,
        csrsrc, csrw, rowp, dinv, (const float4*)b[0],
        (const float4*)gg[0], (const float4*)bb[0], (const float4*)mm[0], (const float4*)vv[0],
        (float4*)h, N);

    // ---- Layer 2: 64 -> 128, BN+ReLU ----
    launch_gemm<64, 128, true>(h, w[1], dinv, xs, N, 0);
    gather_kernel<128, true, false><<<gather_blocks, 256>>>((const float4*)xs,
        csrsrc, csrw, rowp, dinv, (const float4*)b[1],
        (const float4*)gg[1], (const float4*)bb[1], (const float4*)mm[1], (const float4*)vv[1],
        (float4*)h, N);

    // ---- Layer 3: 128 -> 64, BN+ReLU ----
    launch_gemm<128, 64, true>(h, w[2], dinv, xs, N, 0);
    gather_kernel<64, true, false><<<gather_blocks, 256>>>((const float4*)xs,
        csrsrc, csrw, rowp, dinv, (const float4*)b[2],
        (const float4*)gg[2], (const float4*)bb[2], (const float4*)mm[2], (const float4*)vv[2],
        (float4*)h, N);

    // ---- Layer 4: 64 -> 32, BN+ReLU ----
    launch_gemm<64, 32, true>(h, w[3], dinv, xs, N, 0);
    gather_kernel<32, true, false><<<gather_blocks, 256>>>((const float4*)xs,
        csrsrc, csrw, rowp, dinv, (const float4*)b[3],
        (const float4*)gg[3], (const float4*)bb[3], (const float4*)mm[3], (const float4*)vv[3],
        (float4*)h, N);

    // ---- Layer 5: 32 -> 16, no BN, write d_out ----
    float* out = (float*)d_out;
    launch_gemm<32, 16, true>(h, w[4], dinv, xs, N, 0);
    gather_kernel<16, false, false><<<gather_blocks, 256>>>((const float4*)xs,
        csrsrc, csrw, rowp, dinv, (const float4*)b[4],
        nullptr, nullptr, nullptr, nullptr,
        (float4*)out, N);
}